// round 1
// baseline (speedup 1.0000x reference)
#include <cuda_runtime.h>

#define NCAP 50176
#define ECAP 1700000
#define H 64
#define NCONV 6

// ---------------- static device scratch (no allocations allowed) ----------------
__device__ int   g_deg[NCAP];
__device__ float g_sgn[NCAP];
__device__ int   g_offs[NCAP + 1];
__device__ int   g_cursor[NCAP];
__device__ int   g_csr[ECAP];
__device__ float g_inv[NCAP];
__device__ float g_m[NCAP];
__device__ float g_t[NCAP];
__device__ float g_Sx[NCAP];
__device__ float g_ya[NCAP];
__device__ float g_yb[NCAP];
__device__ float g_buf1[(size_t)NCAP * H];
__device__ float g_buf2[(size_t)NCAP * H];
__device__ float g_G[(size_t)NCAP * 2 * H];
__device__ float g_Wc[NCONV * 2 * H * H];
__device__ int   g_bsum[64];
__device__ int   g_bbase[64];

// ---------------- preprocessing ----------------

__global__ void zero_kernel(int n) {
    int i = blockIdx.x * blockDim.x + threadIdx.x;
    if (i < n) { g_deg[i] = 0; g_sgn[i] = 0.0f; }
}

__global__ void deg_kernel(const int* __restrict__ ei, int E) {
    int e = blockIdx.x * blockDim.x + threadIdx.x;
    if (e >= E) return;
    int s = ei[e];
    int d = ei[E + e];
    atomicAdd(&g_deg[d], 1);
    float sg = (s > d) ? 1.0f : ((s < d) ? -1.0f : 0.0f);
    atomicAdd(&g_sgn[d], sg);
}

// per-1024-block exclusive scan of g_deg into g_offs (local), block totals into g_bsum
__global__ void scanA_kernel(int n) {
    __shared__ int sm[32];
    int tid = threadIdx.x;
    int lane = tid & 31, wid = tid >> 5;
    int i = blockIdx.x * 1024 + tid;
    int v = (i < n) ? g_deg[i] : 0;
    int incl = v;
#pragma unroll
    for (int o = 1; o < 32; o <<= 1) {
        int u = __shfl_up_sync(0xffffffffu, incl, o);
        if (lane >= o) incl += u;
    }
    if (lane == 31) sm[wid] = incl;
    __syncthreads();
    if (wid == 0) {
        int t = sm[lane];
#pragma unroll
        for (int o = 1; o < 32; o <<= 1) {
            int u = __shfl_up_sync(0xffffffffu, t, o);
            if (lane >= o) t += u;
        }
        sm[lane] = t;
    }
    __syncthreads();
    int base = (wid > 0) ? sm[wid - 1] : 0;
    if (i < n) g_offs[i] = base + incl - v;
    if (tid == 0) g_bsum[blockIdx.x] = sm[31];
}

__global__ void scanB_kernel(int nb, int n) {
    if (threadIdx.x == 0 && blockIdx.x == 0) {
        int r = 0;
        for (int b = 0; b < nb; b++) { g_bbase[b] = r; r += g_bsum[b]; }
        g_offs[n] = r;
    }
}

__global__ void p3_kernel(int n) {
    int i = blockIdx.x * blockDim.x + threadIdx.x;
    if (i >= n) return;
    int off = g_offs[i] + g_bbase[i >> 10];
    g_offs[i] = off;
    g_cursor[i] = off;
    int d = g_deg[i];
    float inv = 1.0f / fmaxf((float)d, 1.0f);
    g_inv[i] = inv;
    g_m[i] = d > 0 ? 1.0f : 0.0f;
    g_t[i] = inv * g_sgn[i];
}

__global__ void csr_fill_kernel(const int* __restrict__ ei, int E) {
    int e = blockIdx.x * blockDim.x + threadIdx.x;
    if (e >= E) return;
    int s = ei[e];
    int d = ei[E + e];
    int pos = atomicAdd(&g_cursor[d], 1);
    g_csr[pos] = s;
}

// build combined weights Wc[conv][k][c]: rows 0..63 = W1-W2, rows 64..127 = W2
__global__ void wprep_kernel(const float* __restrict__ Wmid) {
    int idx = blockIdx.x * blockDim.x + threadIdx.x;
    if (idx >= NCONV * 2 * H * H) return;
    int conv = idx / (2 * H * H);
    int r = (idx / H) % (2 * H);
    int c = idx % H;
    float v = Wmid[((size_t)conv * 129 + r) * H + c];
    if (r < H) v -= Wmid[((size_t)conv * 129 + H + r) * H + c];
    g_Wc[idx] = v;
}

// ---------------- input layer ----------------

// scalar gather: g_Sx[i] = sum over incoming edges of x[src]
__global__ void sgather_kernel(const float* __restrict__ vals, int n) {
    int i = blockIdx.x * blockDim.x + threadIdx.x;
    if (i >= n) return;
    int k = g_offs[i], e = g_offs[i + 1];
    float s0 = 0, s1 = 0, s2 = 0, s3 = 0;
    for (; k + 4 <= e; k += 4) {
        s0 += vals[g_csr[k]];
        s1 += vals[g_csr[k + 1]];
        s2 += vals[g_csr[k + 2]];
        s3 += vals[g_csr[k + 3]];
    }
    for (; k < e; ++k) s0 += vals[g_csr[k]];
    g_Sx[i] = (s0 + s1) + (s2 + s3);
}

__global__ void kin_kernel(const float* __restrict__ x, const float* __restrict__ Win,
                           const float* __restrict__ bin, int n) {
    long long idx = (long long)blockIdx.x * blockDim.x + threadIdx.x;
    if (idx >= (long long)n * H) return;
    int i = (int)(idx >> 6);
    int c = (int)(idx & 63);
    float w1 = Win[c], w2 = Win[H + c], w3 = Win[2 * H + c];
    float val = g_m[i] * (x[i] * (w1 - w2) + bin[c]) + g_inv[i] * g_Sx[i] * w2 + g_t[i] * w3;
    g_buf2[idx] = val;
}

// ---------------- mid layers ----------------

// warp-per-node neighbor gather: G[i] = [ m*x_i | invdeg * sum_j x_j ]
__global__ void gather_kernel(int sel, int n) {
    int warp = (blockIdx.x * blockDim.x + threadIdx.x) >> 5;
    int lane = threadIdx.x & 31;
    if (warp >= n) return;
    const float* xin = sel ? g_buf1 : g_buf2;
    const float2* X = (const float2*)xin;
    int k = g_offs[warp], e = g_offs[warp + 1];
    float2 a0 = make_float2(0.f, 0.f), a1 = a0, a2 = a0, a3 = a0;
    for (; k + 4 <= e; k += 4) {
        int j0 = g_csr[k], j1 = g_csr[k + 1], j2 = g_csr[k + 2], j3 = g_csr[k + 3];
        float2 v0 = X[j0 * 32 + lane];
        float2 v1 = X[j1 * 32 + lane];
        float2 v2 = X[j2 * 32 + lane];
        float2 v3 = X[j3 * 32 + lane];
        a0.x += v0.x; a0.y += v0.y;
        a1.x += v1.x; a1.y += v1.y;
        a2.x += v2.x; a2.y += v2.y;
        a3.x += v3.x; a3.y += v3.y;
    }
    for (; k < e; ++k) {
        int j = g_csr[k];
        float2 v = X[j * 32 + lane];
        a0.x += v.x; a0.y += v.y;
    }
    float sx = (a0.x + a1.x) + (a2.x + a3.x);
    float sy = (a0.y + a1.y) + (a2.y + a3.y);
    float m = g_m[warp], inv = g_inv[warp];
    float2 xi = X[warp * 32 + lane];
    float2* Gr = (float2*)(g_G + (size_t)warp * (2 * H));
    Gr[lane] = make_float2(m * xi.x, m * xi.y);
    Gr[32 + lane] = make_float2(inv * sx, inv * sy);
}

// out[i][c] = leaky( G[i] @ Wc[conv] + m*b[c] + t*w3[c] (+ residual) )
__global__ void gemm_kernel(int conv, const float* __restrict__ bias,
                            const float* __restrict__ wsgn, int n,
                            int out_sel, int res_flag) {
    __shared__ float Ws[2 * H * H];
    int tid = threadIdx.x;
    const float* Wcp = g_Wc + (size_t)conv * (2 * H * H);
    for (int idx = tid; idx < 2 * H * H; idx += 256) Ws[idx] = Wcp[idx];
    __syncthreads();
    int cg = tid & 15, rq = tid >> 4;
    int r0 = blockIdx.x * 128 + rq * 8;
    float acc[8][4];
#pragma unroll
    for (int i = 0; i < 8; i++)
#pragma unroll
        for (int j = 0; j < 4; j++) acc[i][j] = 0.f;
    const float4* Ws4 = (const float4*)Ws;
#pragma unroll 4
    for (int k4 = 0; k4 < 32; k4++) {
        float4 w0 = Ws4[(k4 * 4 + 0) * 16 + cg];
        float4 w1 = Ws4[(k4 * 4 + 1) * 16 + cg];
        float4 w2 = Ws4[(k4 * 4 + 2) * 16 + cg];
        float4 w3 = Ws4[(k4 * 4 + 3) * 16 + cg];
#pragma unroll
        for (int i = 0; i < 8; i++) {
            float4 g = __ldg((const float4*)(g_G + (size_t)(r0 + i) * 128) + k4);
            acc[i][0] += g.x * w0.x + g.y * w1.x + g.z * w2.x + g.w * w3.x;
            acc[i][1] += g.x * w0.y + g.y * w1.y + g.z * w2.y + g.w * w3.y;
            acc[i][2] += g.x * w0.z + g.y * w1.z + g.z * w2.z + g.w * w3.z;
            acc[i][3] += g.x * w0.w + g.y * w1.w + g.z * w2.w + g.w * w3.w;
        }
    }
    float* out = out_sel ? g_buf2 : g_buf1;
    int c0 = cg * 4;
    float b0 = bias[c0], b1 = bias[c0 + 1], b2 = bias[c0 + 2], b3 = bias[c0 + 3];
    float q0 = wsgn[c0], q1 = wsgn[c0 + 1], q2 = wsgn[c0 + 2], q3 = wsgn[c0 + 3];
#pragma unroll
    for (int i = 0; i < 8; i++) {
        int r = r0 + i;
        if (r >= n) break;
        float m = g_m[r], t = g_t[r];
        float o0 = acc[i][0] + m * b0 + t * q0;
        float o1 = acc[i][1] + m * b1 + t * q1;
        float o2 = acc[i][2] + m * b2 + t * q2;
        float o3 = acc[i][3] + m * b3 + t * q3;
        if (res_flag) {
            float4 rv = *(const float4*)(g_buf2 + (size_t)r * H + c0);
            o0 += rv.x; o1 += rv.y; o2 += rv.z; o3 += rv.w;
        }
        o0 = o0 > 0.f ? o0 : 0.01f * o0;
        o1 = o1 > 0.f ? o1 : 0.01f * o1;
        o2 = o2 > 0.f ? o2 : 0.01f * o2;
        o3 = o3 > 0.f ? o3 : 0.01f * o3;
        *(float4*)(out + (size_t)r * H + c0) = make_float4(o0, o1, o2, o3);
    }
}

// ---------------- output layer ----------------

// per-node dots: ya = x2 @ (Wout[:64]-Wout[64:128]), yb = x2 @ Wout[64:128]
__global__ void dot_kernel(const float* __restrict__ Wout, int n) {
    int warp = (blockIdx.x * blockDim.x + threadIdx.x) >> 5;
    int lane = threadIdx.x & 31;
    if (warp >= n) return;
    const float2* X = (const float2*)g_buf2;
    float2 v = X[warp * 32 + lane];
    int c0 = 2 * lane, c1 = c0 + 1;
    float b0 = Wout[H + c0], b1 = Wout[H + c1];
    float a0 = Wout[c0] - b0, a1 = Wout[c1] - b1;
    float pa = v.x * a0 + v.y * a1;
    float pb = v.x * b0 + v.y * b1;
#pragma unroll
    for (int o = 16; o > 0; o >>= 1) {
        pa += __shfl_xor_sync(0xffffffffu, pa, o);
        pb += __shfl_xor_sync(0xffffffffu, pb, o);
    }
    if (lane == 0) { g_ya[warp] = pa; g_yb[warp] = pb; }
}

__global__ void final_kernel(const float* __restrict__ x, const float* __restrict__ Wout,
                             const float* __restrict__ bout, float* __restrict__ out, int n) {
    int i = blockIdx.x * blockDim.x + threadIdx.x;
    if (i >= n) return;
    int k = g_offs[i], e = g_offs[i + 1];
    float s0 = 0, s1 = 0, s2 = 0, s3 = 0;
    for (; k + 4 <= e; k += 4) {
        s0 += g_yb[g_csr[k]];
        s1 += g_yb[g_csr[k + 1]];
        s2 += g_yb[g_csr[k + 2]];
        s3 += g_yb[g_csr[k + 3]];
    }
    for (; k < e; ++k) s0 += g_yb[g_csr[k]];
    float S = (s0 + s1) + (s2 + s3);
    out[i] = g_m[i] * (g_ya[i] + bout[0]) + g_inv[i] * S + g_t[i] * Wout[2 * H] + x[i];
}

// ---------------- launch ----------------

extern "C" void kernel_launch(void* const* d_in, const int* in_sizes, int n_in,
                              void* d_out, int out_size) {
    const float* x    = (const float*)d_in[0];
    const int*   ei   = (const int*)d_in[1];
    const float* Win  = (const float*)d_in[2];
    const float* bin  = (const float*)d_in[3];
    const float* Wmid = (const float*)d_in[4];
    const float* bmid = (const float*)d_in[5];
    const float* Wout = (const float*)d_in[6];
    const float* bout = (const float*)d_in[7];
    int N = in_sizes[0];
    int E = in_sizes[1] / 2;
    float* out = (float*)d_out;

    const int TB = 256;
    int nB = (N + TB - 1) / TB;
    int eB = (E + TB - 1) / TB;
    int NB1024 = (N + 1023) / 1024;
    int gw = (N * 32 + TB - 1) / TB;        // warp-per-node grids
    int gemmB = (N + 127) / 128;

    zero_kernel<<<nB, TB>>>(N);
    deg_kernel<<<eB, TB>>>(ei, E);
    scanA_kernel<<<NB1024, 1024>>>(N);
    scanB_kernel<<<1, 1>>>(NB1024, N);
    p3_kernel<<<nB, TB>>>(N);
    csr_fill_kernel<<<eB, TB>>>(ei, E);
    wprep_kernel<<<(NCONV * 2 * H * H + TB - 1) / TB, TB>>>(Wmid);

    // input layer: x (N,1) -> g_buf2 (N,64)
    sgather_kernel<<<nB, TB>>>(x, N);
    kin_kernel<<<(int)(((long long)N * H + TB - 1) / TB), TB>>>(x, Win, bin, N);

    // 3 depth blocks = 6 mid convs
    for (int l = 0; l < 3; l++) {
        int c0 = 2 * l, c1 = 2 * l + 1;
        gather_kernel<<<gw, TB>>>(0, N);  // reads g_buf2
        gemm_kernel<<<gemmB, TB>>>(c0, bmid + (size_t)c0 * H,
                                   Wmid + ((size_t)c0 * 129 + 128) * H, N, 0, 0); // -> g_buf1
        gather_kernel<<<gw, TB>>>(1, N);  // reads g_buf1
        gemm_kernel<<<gemmB, TB>>>(c1, bmid + (size_t)c1 * H,
                                   Wmid + ((size_t)c1 * 129 + 128) * H, N, 1, 1); // -> g_buf2 (+res)
    }

    // output layer
    dot_kernel<<<gw, TB>>>(Wout, N);
    final_kernel<<<nB, TB>>>(x, Wout, bout, out, N);
}